// round 11
// baseline (speedup 1.0000x reference)
#include <cuda_runtime.h>
#include <cuda_bf16.h>

// Problem constants
#define BB 16
#define TT 24
#define NN 2048
#define FF 64
#define BT (BB*TT)          // 384
#define NF (NN*FF)          // 131072
#define NF4 (NF/4)          // 32768 float4 per (b,t) row
#define NOCT 8              // n-range octants per (b,t)

// Scratch (device globals; no allocation allowed). All fully overwritten each call.
__device__ float d_lfp[NOCT*BT*FF];    // lhs_f partials (per octant)
__device__ float d_Gp [NOCT*BT*FF];    // G partials (per octant)
__device__ float d_A  [BB*TT*TT];      // attention weights

// ---------------------------------------------------------------------------
// Kernel 1: single pass over ALL of x; fuses the old k2.
// Each CTA (128 thr) handles one octant (256 rows) of one (b,t).
// grid = BT*8 = 3072 CTAs.
// Per row n (4 lanes/row, 16 floats/lane):
//   d        = sum_f x[n,f]*U3[f]            (2-shuffle reduce + broadcast)
//   acc  [f] += x[n,f]*U1[n]                 (-> lfp partial)
//   acc_g[f] += d * U2[n,f]                  (-> Gp partial; U2 L2-resident)
// ---------------------------------------------------------------------------
__global__ __launch_bounds__(128) void k1_pass(
    const float* __restrict__ x, const float* __restrict__ U1,
    const float* __restrict__ U2, const float* __restrict__ U3,
    float* __restrict__ lfp, float* __restrict__ Gp)
{
    const int bt   = blockIdx.x >> 3;
    const int oct  = blockIdx.x & 7;
    const int w    = threadIdx.x >> 5;
    const int lane = threadIdx.x & 31;
    const int r    = lane >> 2;
    const int q    = lane & 3;
    const float4* xb = (const float4*)(x + (size_t)bt * NF);

    float4 u3[4];
    #pragma unroll
    for (int j = 0; j < 4; j++) u3[j] = ((const float4*)U3)[q + 4*j];

    float4 acc[4], accg[4];
    #pragma unroll
    for (int j = 0; j < 4; j++) {
        acc[j]  = make_float4(0.f,0.f,0.f,0.f);
        accg[j] = make_float4(0.f,0.f,0.f,0.f);
    }

    const int n0 = oct * 256 + w * 64;
    #pragma unroll 4
    for (int k = 0; k < 8; k++) {
        const int n = n0 + 8*k + r;
        const float4* row = xb + (size_t)n * 16;
        const float u1 = __ldg(U1 + n);
        float d = 0.f;
        #pragma unroll
        for (int j = 0; j < 4; j++) {
            float4 v = row[q + 4*j];
            d += v.x*u3[j].x + v.y*u3[j].y + v.z*u3[j].z + v.w*u3[j].w;
            acc[j].x += v.x*u1; acc[j].y += v.y*u1;
            acc[j].z += v.z*u1; acc[j].w += v.w*u1;
        }
        // full row dot within the 4-lane group, then broadcast to all 4 lanes
        d += __shfl_down_sync(0xffffffffu, d, 2, 4);
        d += __shfl_down_sync(0xffffffffu, d, 1, 4);
        d  = __shfl_sync(0xffffffffu, d, lane & ~3);
        // accumulate partial G: d * U2[n, :] (U2 row hits L2/L1)
        const float4* u2row = (const float4*)(U2 + (size_t)n * FF);
        #pragma unroll
        for (int j = 0; j < 4; j++) {
            float4 u2 = __ldg(u2row + q + 4*j);
            accg[j].x += d*u2.x; accg[j].y += d*u2.y;
            accg[j].z += d*u2.z; accg[j].w += d*u2.w;
        }
    }

    // reduce acc and accg across the 8 row-groups (r) within the warp
    #pragma unroll
    for (int off = 16; off >= 4; off >>= 1) {
        #pragma unroll
        for (int j = 0; j < 4; j++) {
            acc[j].x  += __shfl_down_sync(0xffffffffu, acc[j].x,  off);
            acc[j].y  += __shfl_down_sync(0xffffffffu, acc[j].y,  off);
            acc[j].z  += __shfl_down_sync(0xffffffffu, acc[j].z,  off);
            acc[j].w  += __shfl_down_sync(0xffffffffu, acc[j].w,  off);
            accg[j].x += __shfl_down_sync(0xffffffffu, accg[j].x, off);
            accg[j].y += __shfl_down_sync(0xffffffffu, accg[j].y, off);
            accg[j].z += __shfl_down_sync(0xffffffffu, accg[j].z, off);
            accg[j].w += __shfl_down_sync(0xffffffffu, accg[j].w, off);
        }
    }

    __shared__ float sredA[4][FF];
    __shared__ float sredG[4][FF];
    if (lane < 4) {
        #pragma unroll
        for (int j = 0; j < 4; j++) {
            ((float4*)sredA[w])[q + 4*j] = acc[j];
            ((float4*)sredG[w])[q + 4*j] = accg[j];
        }
    }
    __syncthreads();
    if (threadIdx.x < FF) {
        const int f = threadIdx.x;
        float t = 0.f;
        #pragma unroll
        for (int p = 0; p < 4; p++) t += sredA[p][f];
        lfp[(bt*NOCT + oct)*FF + f] = t;
    } else {
        const int f = threadIdx.x - FF;
        float t = 0.f;
        #pragma unroll
        for (int p = 0; p < 4; p++) t += sredG[p][f];
        Gp[(bt*NOCT + oct)*FF + f] = t;
    }
}

// ---------------------------------------------------------------------------
// Kernel 3: per batch: product -> sigmoid(+be) -> E -> softmax.
// lfp and Gp each summed over 8 octant partials.
// ---------------------------------------------------------------------------
__global__ __launch_bounds__(576) void k3_scores(
    const float* __restrict__ lfp, const float* __restrict__ Gp,
    const float* __restrict__ be, const float* __restrict__ Ve,
    float* __restrict__ A)
{
    const int b = blockIdx.x;
    __shared__ float lfs[TT*65], Gs[TT*65], sg[TT*25], Em[TT*25];
    __shared__ float cmax[TT], csum[TT];
    const int tid = threadIdx.x;

    for (int e = tid; e < TT*FF; e += 576) {
        int t = e >> 6, f = e & 63;
        const int bt = b*TT + t;
        float lv = 0.f, gv = 0.f;
        #pragma unroll
        for (int p = 0; p < NOCT; p++) {
            lv += lfp[(bt*NOCT + p)*FF + f];
            gv += Gp [(bt*NOCT + p)*FF + f];
        }
        lfs[t*65 + f] = lv;
        Gs [t*65 + f] = gv;
    }
    __syncthreads();

    const int t = tid / TT;
    const int s = tid % TT;
    float p = 0.f;
    #pragma unroll
    for (int f = 0; f < FF; f++)
        p += lfs[t*65 + f] * Gs[s*65 + f];
    sg[t*25 + s] = 1.f / (1.f + __expf(-(p + be[t*TT + s])));
    __syncthreads();

    float e = 0.f;
    #pragma unroll
    for (int s2 = 0; s2 < TT; s2++)
        e += Ve[t*TT + s2] * sg[s2*25 + s];
    Em[t*25 + s] = e;
    __syncthreads();

    if (t == 0) {
        float m = -1e30f;
        #pragma unroll
        for (int tt2 = 0; tt2 < TT; tt2++) m = fmaxf(m, Em[tt2*25 + s]);
        cmax[s] = m;
    }
    __syncthreads();
    const float ex = __expf(Em[t*25 + s] - cmax[s]);
    Em[t*25 + s] = ex;
    __syncthreads();
    if (t == 0) {
        float sm = 0.f;
        #pragma unroll
        for (int tt2 = 0; tt2 < TT; tt2++) sm += Em[tt2*25 + s];
        csum[s] = sm;
    }
    __syncthreads();
    A[b*TT*TT + t*TT + s] = ex / csum[s];
}

// ---------------------------------------------------------------------------
// Kernel 4: out[b,s,nf] = sum_t x[b,t,nf] * A[b,t,s].
// float4 column per thread (xr = 24 x float4), s in pairs, A as float2 in smem,
// 4 CTAs/SM. Reverse batch order for L2 reuse of k1's tail.
// ---------------------------------------------------------------------------
__global__ __launch_bounds__(128, 4) void k4_out(
    const float4* __restrict__ x4, const float* __restrict__ A,
    float4* __restrict__ out4)
{
    __shared__ float2 As2[TT*12];
    const int b = (BB - 1) - blockIdx.y;
    const float2* Ab2 = (const float2*)(A + b*TT*TT);
    for (int i = threadIdx.x; i < TT*12; i += 128)
        As2[i] = Ab2[i];
    __syncthreads();

    const size_t c = (size_t)blockIdx.x * 128 + threadIdx.x;
    const float4* xb = x4 + (size_t)b * TT * NF4 + c;

    float4 xr[TT];
    #pragma unroll
    for (int t = 0; t < TT; t++) xr[t] = xb[(size_t)t * NF4];

    float4* ob = out4 + (size_t)b * TT * NF4 + c;
    #pragma unroll 1
    for (int sp = 0; sp < 12; sp++) {
        float4 a0 = make_float4(0.f,0.f,0.f,0.f);
        float4 a1 = make_float4(0.f,0.f,0.f,0.f);
        #pragma unroll
        for (int t = 0; t < TT; t++) {
            const float2 av = As2[t*12 + sp];
            a0.x += xr[t].x*av.x; a0.y += xr[t].y*av.x; a0.z += xr[t].z*av.x; a0.w += xr[t].w*av.x;
            a1.x += xr[t].x*av.y; a1.y += xr[t].y*av.y; a1.z += xr[t].z*av.y; a1.w += xr[t].w*av.y;
        }
        ob[(size_t)(2*sp    ) * NF4] = a0;
        ob[(size_t)(2*sp + 1) * NF4] = a1;
    }
}

// ---------------------------------------------------------------------------
extern "C" void kernel_launch(void* const* d_in, const int* in_sizes, int n_in,
                              void* d_out, int out_size)
{
    const float* x  = (const float*)d_in[0];
    const float* U1 = (const float*)d_in[1];
    const float* U2 = (const float*)d_in[2];
    const float* U3 = (const float*)d_in[3];
    const float* be = (const float*)d_in[4];
    const float* Ve = (const float*)d_in[5];

    float *lfp, *Gp, *A;
    cudaGetSymbolAddress((void**)&lfp, d_lfp);
    cudaGetSymbolAddress((void**)&Gp,  d_Gp);
    cudaGetSymbolAddress((void**)&A,   d_A);

    k1_pass<<<BT*NOCT, 128>>>(x, U1, U2, U3, lfp, Gp);
    k3_scores<<<BB, 576>>>(lfp, Gp, be, Ve, A);
    k4_out<<<dim3(NF4/128, BB), 128>>>((const float4*)x, A, (float4*)d_out);
}

// round 12
// speedup vs baseline: 1.0587x; 1.0587x over previous
#include <cuda_runtime.h>
#include <cuda_bf16.h>

// Problem constants
#define BB 16
#define TT 24
#define NN 2048
#define FF 64
#define BT (BB*TT)          // 384
#define NF (NN*FF)          // 131072
#define NF4 (NF/4)          // 32768 float4 per (b,t) row
#define KSPLIT 16

typedef unsigned long long u64t;

// Scratch (device globals; no allocation allowed). All fully overwritten each call.
__device__ float d_rhs[BT*NN];         // 3 MB
__device__ float d_lfp[8*BT*FF];       // lhs_f partials (8 octants per bt)
__device__ float d_Gp [KSPLIT*BT*FF];  // K-split partials of G
__device__ float d_A  [BB*TT*TT];      // attention weights

__device__ __forceinline__ void ffma2(u64t& d, u64t a, u64t b) {
    asm("fma.rn.f32x2 %0, %1, %2, %0;" : "+l"(d) : "l"(a), "l"(b));
}

// ---------------------------------------------------------------------------
// Kernel 1: single pass over ALL of x (R10 proven version).
// Each CTA (128 thr) handles one octant (256 rows) of one (b,t).
// grid = BT*8 = 3072 CTAs.
// ---------------------------------------------------------------------------
__global__ __launch_bounds__(128) void k1_pass(
    const float* __restrict__ x, const float* __restrict__ U1,
    const float* __restrict__ U3, float* __restrict__ rhs,
    float* __restrict__ lfp)
{
    const int bt   = blockIdx.x >> 3;
    const int oct  = blockIdx.x & 7;
    const int w    = threadIdx.x >> 5;
    const int lane = threadIdx.x & 31;
    const int r    = lane >> 2;
    const int q    = lane & 3;
    const float4* xb = (const float4*)(x + (size_t)bt * NF);

    float4 u3[4];
    #pragma unroll
    for (int j = 0; j < 4; j++) u3[j] = ((const float4*)U3)[q + 4*j];

    float4 acc[4];
    #pragma unroll
    for (int j = 0; j < 4; j++) acc[j] = make_float4(0.f,0.f,0.f,0.f);

    const int n0 = oct * 256 + w * 64;
    #pragma unroll 4
    for (int k = 0; k < 8; k++) {
        const int n = n0 + 8*k + r;
        const float4* row = xb + (size_t)n * 16;
        const float u1 = __ldg(U1 + n);
        float d = 0.f;
        #pragma unroll
        for (int j = 0; j < 4; j++) {
            float4 v = row[q + 4*j];
            d += v.x*u3[j].x + v.y*u3[j].y + v.z*u3[j].z + v.w*u3[j].w;
            acc[j].x += v.x*u1; acc[j].y += v.y*u1;
            acc[j].z += v.z*u1; acc[j].w += v.w*u1;
        }
        d += __shfl_down_sync(0xffffffffu, d, 2, 4);
        d += __shfl_down_sync(0xffffffffu, d, 1, 4);
        if (q == 0) rhs[bt*NN + n] = d;
    }

    #pragma unroll
    for (int off = 16; off >= 4; off >>= 1) {
        #pragma unroll
        for (int j = 0; j < 4; j++) {
            acc[j].x += __shfl_down_sync(0xffffffffu, acc[j].x, off);
            acc[j].y += __shfl_down_sync(0xffffffffu, acc[j].y, off);
            acc[j].z += __shfl_down_sync(0xffffffffu, acc[j].z, off);
            acc[j].w += __shfl_down_sync(0xffffffffu, acc[j].w, off);
        }
    }

    __shared__ float sred[4][FF];
    if (lane < 4) {
        #pragma unroll
        for (int j = 0; j < 4; j++)
            ((float4*)sred[w])[q + 4*j] = acc[j];
    }
    __syncthreads();
    if (threadIdx.x < FF) {
        float t = 0.f;
        #pragma unroll
        for (int p = 0; p < 4; p++) t += sred[p][threadIdx.x];
        lfp[(bt*8 + oct)*FF + threadIdx.x] = t;
    }
}

// ---------------------------------------------------------------------------
// Kernel 2: G = rhs(384 x 2048) @ U2(2048 x 64), K-split into 16 partials.
// ---------------------------------------------------------------------------
__global__ __launch_bounds__(128) void k2_gemm(
    const float* __restrict__ rhs, const float* __restrict__ U2,
    float* __restrict__ Gp)
{
    __shared__ float4 Us4[64*16];
    __shared__ float  Rs [32*68];
    const int m0 = blockIdx.x * 32;
    const int k0 = blockIdx.y * 128;
    const int c4 = threadIdx.x & 15;
    const int rg = threadIdx.x >> 4;

    float4 acc[4];
    #pragma unroll
    for (int r = 0; r < 4; r++) acc[r] = make_float4(0.f,0.f,0.f,0.f);

    for (int kc = 0; kc < 128; kc += 64) {
        const int kb = k0 + kc;
        __syncthreads();
        #pragma unroll
        for (int i = 0; i < 8; i++) {
            int e = threadIdx.x + i*128;
            int kk = e >> 4, cc = e & 15;
            Us4[e] = ((const float4*)(U2 + (size_t)(kb + kk)*FF))[cc];
        }
        #pragma unroll
        for (int i = 0; i < 4; i++) {
            int e = threadIdx.x + i*128;
            int row = e >> 4, kq = e & 15;
            float4 v = *(const float4*)(rhs + (size_t)(m0 + row)*NN + kb + kq*4);
            *(float4*)&Rs[row*68 + kq*4] = v;
        }
        __syncthreads();
        #pragma unroll
        for (int kk = 0; kk < 64; kk++) {
            const float4 u = Us4[kk*16 + c4];
            #pragma unroll
            for (int r = 0; r < 4; r++) {
                const float rv = Rs[(rg*4 + r)*68 + kk];
                acc[r].x += rv*u.x; acc[r].y += rv*u.y;
                acc[r].z += rv*u.z; acc[r].w += rv*u.w;
            }
        }
    }
    float* g = Gp + (size_t)blockIdx.y * (BT*FF);
    #pragma unroll
    for (int r = 0; r < 4; r++)
        *(float4*)&g[(m0 + rg*4 + r)*FF + c4*4] = acc[r];
}

// ---------------------------------------------------------------------------
// Kernel 3: per batch: product -> sigmoid(+be) -> E -> softmax (8 lfp partials).
// ---------------------------------------------------------------------------
__global__ __launch_bounds__(576) void k3_scores(
    const float* __restrict__ lfp, const float* __restrict__ Gp,
    const float* __restrict__ be, const float* __restrict__ Ve,
    float* __restrict__ A)
{
    const int b = blockIdx.x;
    __shared__ float lfs[TT*65], Gs[TT*65], sg[TT*25], Em[TT*25];
    __shared__ float cmax[TT], csum[TT];
    const int tid = threadIdx.x;

    for (int e = tid; e < TT*FF; e += 576) {
        int t = e >> 6, f = e & 63;
        const int bt = b*TT + t;
        float lv = 0.f;
        #pragma unroll
        for (int p = 0; p < 8; p++) lv += lfp[(bt*8 + p)*FF + f];
        lfs[t*65 + f] = lv;
        float g = 0.f;
        #pragma unroll
        for (int ks = 0; ks < KSPLIT; ks++)
            g += Gp[(size_t)ks*(BT*FF) + bt*FF + f];
        Gs[t*65 + f] = g;
    }
    __syncthreads();

    const int t = tid / TT;
    const int s = tid % TT;
    float p = 0.f;
    #pragma unroll
    for (int f = 0; f < FF; f++)
        p += lfs[t*65 + f] * Gs[s*65 + f];
    sg[t*25 + s] = 1.f / (1.f + __expf(-(p + be[t*TT + s])));
    __syncthreads();

    float e = 0.f;
    #pragma unroll
    for (int s2 = 0; s2 < TT; s2++)
        e += Ve[t*TT + s2] * sg[s2*25 + s];
    Em[t*25 + s] = e;
    __syncthreads();

    if (t == 0) {
        float m = -1e30f;
        #pragma unroll
        for (int tt2 = 0; tt2 < TT; tt2++) m = fmaxf(m, Em[tt2*25 + s]);
        cmax[s] = m;
    }
    __syncthreads();
    const float ex = __expf(Em[t*25 + s] - cmax[s]);
    Em[t*25 + s] = ex;
    __syncthreads();
    if (t == 0) {
        float sm = 0.f;
        #pragma unroll
        for (int tt2 = 0; tt2 < TT; tt2++) sm += Em[tt2*25 + s];
        csum[s] = sm;
    }
    __syncthreads();
    A[b*TT*TT + t*TT + s] = ex / csum[s];
}

// ---------------------------------------------------------------------------
// Kernel 4: out[b,s,nf] = sum_t x[b,t,nf] * A[b,t,s] with packed f32x2 FMA.
// x column held as 24 x ulonglong2 (96 regs, same layout as float4).
// A staged in smem pre-duplicated as (a0,a0,a1,a1) float4: inner loop per t =
// 1 LDS.128 + 4 FFMA2 (vs 1 LDS.64 + 8 FFMA) -> 44% fewer issue slots.
// Live regs ~120 -> 4 CTAs/SM under __launch_bounds__(128,4).
// ---------------------------------------------------------------------------
__global__ __launch_bounds__(128, 4) void k4_out(
    const ulonglong2* __restrict__ x16, const float* __restrict__ A,
    ulonglong2* __restrict__ out16)
{
    __shared__ float4 As4[TT*12];   // [t][sp] = (A[t,2sp], A[t,2sp], A[t,2sp+1], A[t,2sp+1])
    const int b = (BB - 1) - blockIdx.y;   // reverse batch order for L2 reuse
    const float* Ab = A + b*TT*TT;
    for (int i = threadIdx.x; i < TT*12; i += 128) {
        const int t  = i / 12;
        const int sp = i % 12;
        const float a0 = Ab[t*TT + 2*sp];
        const float a1 = Ab[t*TT + 2*sp + 1];
        As4[i] = make_float4(a0, a0, a1, a1);
    }
    __syncthreads();

    const size_t c = (size_t)blockIdx.x * 128 + threadIdx.x;  // 16B column
    const ulonglong2* xb = x16 + (size_t)b * TT * NF4 + c;

    ulonglong2 xr[TT];
    #pragma unroll
    for (int t = 0; t < TT; t++) xr[t] = xb[(size_t)t * NF4];

    ulonglong2* ob = out16 + (size_t)b * TT * NF4 + c;
    #pragma unroll 1
    for (int sp = 0; sp < 12; sp++) {
        u64t a0lo = 0ull, a0hi = 0ull, a1lo = 0ull, a1hi = 0ull;
        #pragma unroll
        for (int t = 0; t < TT; t++) {
            const ulonglong2 aa = *(const ulonglong2*)&As4[t*12 + sp];
            ffma2(a0lo, xr[t].x, aa.x);
            ffma2(a0hi, xr[t].y, aa.x);
            ffma2(a1lo, xr[t].x, aa.y);
            ffma2(a1hi, xr[t].y, aa.y);
        }
        ob[(size_t)(2*sp    ) * NF4] = make_ulonglong2(a0lo, a0hi);
        ob[(size_t)(2*sp + 1) * NF4] = make_ulonglong2(a1lo, a1hi);
    }
}

// ---------------------------------------------------------------------------
extern "C" void kernel_launch(void* const* d_in, const int* in_sizes, int n_in,
                              void* d_out, int out_size)
{
    const float* x  = (const float*)d_in[0];
    const float* U1 = (const float*)d_in[1];
    const float* U2 = (const float*)d_in[2];
    const float* U3 = (const float*)d_in[3];
    const float* be = (const float*)d_in[4];
    const float* Ve = (const float*)d_in[5];

    float *rhs, *lfp, *Gp, *A;
    cudaGetSymbolAddress((void**)&rhs, d_rhs);
    cudaGetSymbolAddress((void**)&lfp, d_lfp);
    cudaGetSymbolAddress((void**)&Gp,  d_Gp);
    cudaGetSymbolAddress((void**)&A,   d_A);

    k1_pass<<<BT*8, 128>>>(x, U1, U3, rhs, lfp);
    k2_gemm<<<dim3(BT/32, KSPLIT), 128>>>(rhs, U2, Gp);
    k3_scores<<<BB, 576>>>(lfp, Gp, be, Ve, A);
    k4_out<<<dim3(NF4/128, BB), 128>>>((const ulonglong2*)x, A, (ulonglong2*)d_out);
}

// round 13
// speedup vs baseline: 1.0895x; 1.0291x over previous
#include <cuda_runtime.h>
#include <cuda_bf16.h>

// Problem constants
#define BB 16
#define TT 24
#define NN 2048
#define FF 64
#define BT (BB*TT)          // 384
#define NF (NN*FF)          // 131072
#define NF4 (NF/4)          // 32768 float4 per (b,t) row
#define KSPLIT 16

// Scratch (device globals; no allocation allowed). All fully overwritten each call.
__device__ float d_rhs[BT*NN];         // 3 MB
__device__ float d_lfp[8*BT*FF];       // lhs_f partials (8 octants per bt)
__device__ float d_Gp [KSPLIT*BT*FF];  // K-split partials of G
__device__ float d_A  [BB*TT*TT];      // attention weights

// Streaming store (evict-first): out is never re-read, keep it from evicting x.
__device__ __forceinline__ void stcs4(float4* p, float4 v) {
    asm volatile("st.global.cs.v4.f32 [%0], {%1,%2,%3,%4};"
                 :: "l"(p), "f"(v.x), "f"(v.y), "f"(v.z), "f"(v.w) : "memory");
}

// ---------------------------------------------------------------------------
// Kernel 1: single pass over ALL of x (R10 proven version).
// Each CTA (128 thr) handles one octant (256 rows) of one (b,t).
// grid = BT*8 = 3072 CTAs.
// ---------------------------------------------------------------------------
__global__ __launch_bounds__(128) void k1_pass(
    const float* __restrict__ x, const float* __restrict__ U1,
    const float* __restrict__ U3, float* __restrict__ rhs,
    float* __restrict__ lfp)
{
    const int bt   = blockIdx.x >> 3;
    const int oct  = blockIdx.x & 7;
    const int w    = threadIdx.x >> 5;
    const int lane = threadIdx.x & 31;
    const int r    = lane >> 2;
    const int q    = lane & 3;
    const float4* xb = (const float4*)(x + (size_t)bt * NF);

    float4 u3[4];
    #pragma unroll
    for (int j = 0; j < 4; j++) u3[j] = ((const float4*)U3)[q + 4*j];

    float4 acc[4];
    #pragma unroll
    for (int j = 0; j < 4; j++) acc[j] = make_float4(0.f,0.f,0.f,0.f);

    const int n0 = oct * 256 + w * 64;
    #pragma unroll 4
    for (int k = 0; k < 8; k++) {
        const int n = n0 + 8*k + r;
        const float4* row = xb + (size_t)n * 16;
        const float u1 = __ldg(U1 + n);
        float d = 0.f;
        #pragma unroll
        for (int j = 0; j < 4; j++) {
            float4 v = row[q + 4*j];
            d += v.x*u3[j].x + v.y*u3[j].y + v.z*u3[j].z + v.w*u3[j].w;
            acc[j].x += v.x*u1; acc[j].y += v.y*u1;
            acc[j].z += v.z*u1; acc[j].w += v.w*u1;
        }
        d += __shfl_down_sync(0xffffffffu, d, 2, 4);
        d += __shfl_down_sync(0xffffffffu, d, 1, 4);
        if (q == 0) rhs[bt*NN + n] = d;
    }

    #pragma unroll
    for (int off = 16; off >= 4; off >>= 1) {
        #pragma unroll
        for (int j = 0; j < 4; j++) {
            acc[j].x += __shfl_down_sync(0xffffffffu, acc[j].x, off);
            acc[j].y += __shfl_down_sync(0xffffffffu, acc[j].y, off);
            acc[j].z += __shfl_down_sync(0xffffffffu, acc[j].z, off);
            acc[j].w += __shfl_down_sync(0xffffffffu, acc[j].w, off);
        }
    }

    __shared__ float sred[4][FF];
    if (lane < 4) {
        #pragma unroll
        for (int j = 0; j < 4; j++)
            ((float4*)sred[w])[q + 4*j] = acc[j];
    }
    __syncthreads();
    if (threadIdx.x < FF) {
        float t = 0.f;
        #pragma unroll
        for (int p = 0; p < 4; p++) t += sred[p][threadIdx.x];
        lfp[(bt*8 + oct)*FF + threadIdx.x] = t;
    }
}

// ---------------------------------------------------------------------------
// Kernel 2: G = rhs(384 x 2048) @ U2(2048 x 64), K-split into 16 partials.
// ---------------------------------------------------------------------------
__global__ __launch_bounds__(128) void k2_gemm(
    const float* __restrict__ rhs, const float* __restrict__ U2,
    float* __restrict__ Gp)
{
    __shared__ float4 Us4[64*16];
    __shared__ float  Rs [32*68];
    const int m0 = blockIdx.x * 32;
    const int k0 = blockIdx.y * 128;
    const int c4 = threadIdx.x & 15;
    const int rg = threadIdx.x >> 4;

    float4 acc[4];
    #pragma unroll
    for (int r = 0; r < 4; r++) acc[r] = make_float4(0.f,0.f,0.f,0.f);

    for (int kc = 0; kc < 128; kc += 64) {
        const int kb = k0 + kc;
        __syncthreads();
        #pragma unroll
        for (int i = 0; i < 8; i++) {
            int e = threadIdx.x + i*128;
            int kk = e >> 4, cc = e & 15;
            Us4[e] = ((const float4*)(U2 + (size_t)(kb + kk)*FF))[cc];
        }
        #pragma unroll
        for (int i = 0; i < 4; i++) {
            int e = threadIdx.x + i*128;
            int row = e >> 4, kq = e & 15;
            float4 v = *(const float4*)(rhs + (size_t)(m0 + row)*NN + kb + kq*4);
            *(float4*)&Rs[row*68 + kq*4] = v;
        }
        __syncthreads();
        #pragma unroll
        for (int kk = 0; kk < 64; kk++) {
            const float4 u = Us4[kk*16 + c4];
            #pragma unroll
            for (int r = 0; r < 4; r++) {
                const float rv = Rs[(rg*4 + r)*68 + kk];
                acc[r].x += rv*u.x; acc[r].y += rv*u.y;
                acc[r].z += rv*u.z; acc[r].w += rv*u.w;
            }
        }
    }
    float* g = Gp + (size_t)blockIdx.y * (BT*FF);
    #pragma unroll
    for (int r = 0; r < 4; r++)
        *(float4*)&g[(m0 + rg*4 + r)*FF + c4*4] = acc[r];
}

// ---------------------------------------------------------------------------
// Kernel 3: per batch: product -> sigmoid(+be) -> E -> softmax (8 lfp partials).
// ---------------------------------------------------------------------------
__global__ __launch_bounds__(576) void k3_scores(
    const float* __restrict__ lfp, const float* __restrict__ Gp,
    const float* __restrict__ be, const float* __restrict__ Ve,
    float* __restrict__ A)
{
    const int b = blockIdx.x;
    __shared__ float lfs[TT*65], Gs[TT*65], sg[TT*25], Em[TT*25];
    __shared__ float cmax[TT], csum[TT];
    const int tid = threadIdx.x;

    for (int e = tid; e < TT*FF; e += 576) {
        int t = e >> 6, f = e & 63;
        const int bt = b*TT + t;
        float lv = 0.f;
        #pragma unroll
        for (int p = 0; p < 8; p++) lv += lfp[(bt*8 + p)*FF + f];
        lfs[t*65 + f] = lv;
        float g = 0.f;
        #pragma unroll
        for (int ks = 0; ks < KSPLIT; ks++)
            g += Gp[(size_t)ks*(BT*FF) + bt*FF + f];
        Gs[t*65 + f] = g;
    }
    __syncthreads();

    const int t = tid / TT;
    const int s = tid % TT;
    float p = 0.f;
    #pragma unroll
    for (int f = 0; f < FF; f++)
        p += lfs[t*65 + f] * Gs[s*65 + f];
    sg[t*25 + s] = 1.f / (1.f + __expf(-(p + be[t*TT + s])));
    __syncthreads();

    float e = 0.f;
    #pragma unroll
    for (int s2 = 0; s2 < TT; s2++)
        e += Ve[t*TT + s2] * sg[s2*25 + s];
    Em[t*25 + s] = e;
    __syncthreads();

    if (t == 0) {
        float m = -1e30f;
        #pragma unroll
        for (int tt2 = 0; tt2 < TT; tt2++) m = fmaxf(m, Em[tt2*25 + s]);
        cmax[s] = m;
    }
    __syncthreads();
    const float ex = __expf(Em[t*25 + s] - cmax[s]);
    Em[t*25 + s] = ex;
    __syncthreads();
    if (t == 0) {
        float sm = 0.f;
        #pragma unroll
        for (int tt2 = 0; tt2 < TT; tt2++) sm += Em[tt2*25 + s];
        csum[s] = sm;
    }
    __syncthreads();
    A[b*TT*TT + t*TT + s] = ex / csum[s];
}

// ---------------------------------------------------------------------------
// Kernel 4: out[b,s,nf] = sum_t x[b,t,nf] * A[b,t,s].
// R10 proven structure: float4 column per thread (xr = 24 x float4), s in
// pairs, A as float2 in smem, 4 CTAs/SM, reverse batch order.
// NEW: out stored with st.global.cs (evict-first) so the 201 MB of dead
// output lines don't evict x from L2.
// ---------------------------------------------------------------------------
__global__ __launch_bounds__(128, 4) void k4_out(
    const float4* __restrict__ x4, const float* __restrict__ A,
    float4* __restrict__ out4)
{
    __shared__ float2 As2[TT*12];
    const int b = (BB - 1) - blockIdx.y;
    const float2* Ab2 = (const float2*)(A + b*TT*TT);
    for (int i = threadIdx.x; i < TT*12; i += 128)
        As2[i] = Ab2[i];
    __syncthreads();

    const size_t c = (size_t)blockIdx.x * 128 + threadIdx.x;
    const float4* xb = x4 + (size_t)b * TT * NF4 + c;

    float4 xr[TT];
    #pragma unroll
    for (int t = 0; t < TT; t++) xr[t] = xb[(size_t)t * NF4];

    float4* ob = out4 + (size_t)b * TT * NF4 + c;
    #pragma unroll 1
    for (int sp = 0; sp < 12; sp++) {
        float4 a0 = make_float4(0.f,0.f,0.f,0.f);
        float4 a1 = make_float4(0.f,0.f,0.f,0.f);
        #pragma unroll
        for (int t = 0; t < TT; t++) {
            const float2 av = As2[t*12 + sp];
            a0.x += xr[t].x*av.x; a0.y += xr[t].y*av.x; a0.z += xr[t].z*av.x; a0.w += xr[t].w*av.x;
            a1.x += xr[t].x*av.y; a1.y += xr[t].y*av.y; a1.z += xr[t].z*av.y; a1.w += xr[t].w*av.y;
        }
        stcs4(ob + (size_t)(2*sp    ) * NF4, a0);
        stcs4(ob + (size_t)(2*sp + 1) * NF4, a1);
    }
}

// ---------------------------------------------------------------------------
extern "C" void kernel_launch(void* const* d_in, const int* in_sizes, int n_in,
                              void* d_out, int out_size)
{
    const float* x  = (const float*)d_in[0];
    const float* U1 = (const float*)d_in[1];
    const float* U2 = (const float*)d_in[2];
    const float* U3 = (const float*)d_in[3];
    const float* be = (const float*)d_in[4];
    const float* Ve = (const float*)d_in[5];

    float *rhs, *lfp, *Gp, *A;
    cudaGetSymbolAddress((void**)&rhs, d_rhs);
    cudaGetSymbolAddress((void**)&lfp, d_lfp);
    cudaGetSymbolAddress((void**)&Gp,  d_Gp);
    cudaGetSymbolAddress((void**)&A,   d_A);

    k1_pass<<<BT*8, 128>>>(x, U1, U3, rhs, lfp);
    k2_gemm<<<dim3(BT/32, KSPLIT), 128>>>(rhs, U2, Gp);
    k3_scores<<<BB, 576>>>(lfp, Gp, be, Ve, A);
    k4_out<<<dim3(NF4/128, BB), 128>>>((const float4*)x, A, (float4*)d_out);
}